// round 4
// baseline (speedup 1.0000x reference)
#include <cuda_runtime.h>
#include <cuda_bf16.h>
#include <cstdint>
#include <cstddef>

#define DMODEL 1024
#define FDIM   4096
#define NEXP   8
#define NMAX   4096

#define BM 128
#define BN 64
#define BK 32
#define PAD 4
#define KSTR (BK + PAD)   // 36 words: conflict-free for STS.128 and frag LDS

// ---------------- device scratch (static allocations only) ----------------
__device__ float d_H[(size_t)NMAX * FDIM];   // 64 MB intermediate H = silu(u)*v
__device__ int   d_idx[NMAX];
__device__ float d_prob[NMAX];
__device__ int   d_counts[NEXP];
__device__ float d_imp[NEXP];
__device__ int   d_offsets[NEXP + 1];
__device__ int   d_cursor[NEXP];
__device__ int   d_perm[NMAX];

// ---------------- small helpers ----------------
__device__ __forceinline__ uint32_t f2tf32(float f) {
    uint32_t r;
    asm volatile("cvt.rna.tf32.f32 %0, %1;" : "=r"(r) : "f"(f));
    return r;
}
__device__ __forceinline__ void cp16(float* s, const float* g) {
    uint32_t sa = (uint32_t)__cvta_generic_to_shared(s);
    asm volatile("cp.async.cg.shared.global [%0], [%1], 16;" :: "r"(sa), "l"(g));
}
__device__ __forceinline__ void cp_commit() { asm volatile("cp.async.commit_group;"); }
__device__ __forceinline__ void cp_wait0()  { asm volatile("cp.async.wait_group 0;" ::: "memory"); }

// D += A(16x8) * B(8x8), tf32, f32 accum
__device__ __forceinline__ void mma8(float* c, const uint32_t* a, uint32_t b0, uint32_t b1) {
    asm volatile(
        "mma.sync.aligned.m16n8k8.row.col.f32.tf32.tf32.f32 "
        "{%0,%1,%2,%3},{%4,%5,%6,%7},{%8,%9},{%0,%1,%2,%3};"
        : "+f"(c[0]), "+f"(c[1]), "+f"(c[2]), "+f"(c[3])
        : "r"(a[0]), "r"(a[1]), "r"(a[2]), "r"(a[3]), "r"(b0), "r"(b1));
}

// ---------------- kernels ----------------
__global__ void init_kernel() {
    int t = threadIdx.x;
    if (t < NEXP) { d_counts[t] = 0; d_imp[t] = 0.f; }
}

// one warp per token: logits, softmax, top-1, importance + counts
__global__ void gating_kernel(const float* __restrict__ x,
                              const float* __restrict__ gw, int N) {
    __shared__ float sgw[NEXP * DMODEL];    // 32 KB
    __shared__ float s_imp[NEXP];
    __shared__ int   s_cnt[NEXP];
    int tid = threadIdx.x;
    for (int i = tid; i < NEXP * DMODEL; i += blockDim.x) sgw[i] = gw[i];
    if (tid < NEXP) { s_imp[tid] = 0.f; s_cnt[tid] = 0; }
    __syncthreads();

    int warp = tid >> 5, lane = tid & 31;
    int n = blockIdx.x * 8 + warp;
    if (n < N) {
        float acc[NEXP];
        #pragma unroll
        for (int e = 0; e < NEXP; e++) acc[e] = 0.f;
        const float* xr = x + (size_t)n * DMODEL;
        for (int i = lane; i < DMODEL; i += 32) {
            float xv = xr[i];
            #pragma unroll
            for (int e = 0; e < NEXP; e++) acc[e] += xv * sgw[e * DMODEL + i];
        }
        #pragma unroll
        for (int e = 0; e < NEXP; e++) {
            #pragma unroll
            for (int o = 16; o > 0; o >>= 1)
                acc[e] += __shfl_down_sync(0xffffffffu, acc[e], o);
        }
        if (lane == 0) {
            float m = acc[0]; int am = 0;
            #pragma unroll
            for (int e = 1; e < NEXP; e++) if (acc[e] > m) { m = acc[e]; am = e; }
            float p[NEXP]; float s = 0.f;
            #pragma unroll
            for (int e = 0; e < NEXP; e++) { p[e] = expf(acc[e] - m); s += p[e]; }
            float inv = 1.f / s;
            #pragma unroll
            for (int e = 0; e < NEXP; e++) atomicAdd(&s_imp[e], p[e] * inv);
            d_idx[n]  = am;
            d_prob[n] = p[am] * inv;
            atomicAdd(&s_cnt[am], 1);
        }
    }
    __syncthreads();
    if (tid < NEXP) {
        atomicAdd(&d_imp[tid],    s_imp[tid]);
        atomicAdd(&d_counts[tid], s_cnt[tid]);
    }
}

__global__ void offsets_kernel(int N, float* aux_out) {
    if (threadIdx.x == 0) {
        int off = 0;
        #pragma unroll
        for (int e = 0; e < NEXP; e++) {
            d_offsets[e] = off; off += d_counts[e]; d_cursor[e] = 0;
        }
        d_offsets[NEXP] = off;
        if (aux_out) {
            float invN = 1.f / (float)N;
            float aux = 0.f;
            #pragma unroll
            for (int e = 0; e < NEXP; e++)
                aux += ((float)d_counts[e] * invN) * (d_imp[e] * invN);
            *aux_out = aux * (float)NEXP * 0.01f;
        }
    }
}

__global__ void scatter_kernel(int N) {
    int n = blockIdx.x * blockDim.x + threadIdx.x;
    if (n < N) {
        int e = d_idx[n];
        int pos = d_offsets[e] + atomicAdd(&d_cursor[e], 1);
        d_perm[pos] = n;
    }
}

// H[slot, n0:n0+BN] = silu(X W1^T) * (X W3^T)   (grouped by expert)
__global__ __launch_bounds__(256, 1)
void gemm1_kernel(const float* __restrict__ x,
                  const float* __restrict__ w1,
                  const float* __restrict__ w3) {
    int e   = blockIdx.z;
    int off = d_offsets[e];
    int cnt = d_offsets[e + 1] - off;
    int m0  = blockIdx.y * BM;
    if (m0 >= cnt) return;
    int n0 = blockIdx.x * BN;

    extern __shared__ float smem[];
    float* As   = smem;                    // [2][BM][KSTR]
    float* B1s  = As  + 2 * BM * KSTR;     // [2][BN][KSTR]
    float* B3s  = B1s + 2 * BN * KSTR;     // [2][BN][KSTR]
    int*   rows = (int*)(B3s + 2 * BN * KSTR);

    int tid = threadIdx.x;
    for (int i = tid; i < BM; i += 256) {
        int mi = m0 + i;
        rows[i] = d_perm[off + (mi < cnt ? mi : 0)];
    }
    __syncthreads();

    auto load_stage = [&](int kk, int buf) {
        #pragma unroll
        for (int p = 0; p < 4; p++) {
            int idx = p * 256 + tid;
            int m = idx >> 3, kq = idx & 7;
            cp16(&As[(buf * BM + m) * KSTR + kq * 4],
                 x + (size_t)rows[m] * DMODEL + kk + kq * 4);
        }
        #pragma unroll
        for (int p = 0; p < 2; p++) {
            int idx = p * 256 + tid;
            int n = idx >> 3, kq = idx & 7;
            size_t gb = ((size_t)e * FDIM + n0 + n) * DMODEL + kk + kq * 4;
            cp16(&B1s[(buf * BN + n) * KSTR + kq * 4], w1 + gb);
            cp16(&B3s[(buf * BN + n) * KSTR + kq * 4], w3 + gb);
        }
        cp_commit();
    };
    load_stage(0, 0);

    float uacc[2][4][4], vacc[2][4][4];
    #pragma unroll
    for (int a1 = 0; a1 < 2; a1++)
        #pragma unroll
        for (int a2 = 0; a2 < 4; a2++)
            #pragma unroll
            for (int a3 = 0; a3 < 4; a3++) { uacc[a1][a2][a3] = 0.f; vacc[a1][a2][a3] = 0.f; }

    int warp = tid >> 5, lane = tid & 31;
    int wm = warp >> 1, wn = warp & 1;    // 4 x 2 warp grid
    int g = lane >> 2, c = lane & 3;

    const int NIT = DMODEL / BK;          // 32
    for (int it = 0; it < NIT; it++) {
        int buf = it & 1;
        cp_wait0();
        __syncthreads();
        if (it + 1 < NIT) load_stage((it + 1) * BK, buf ^ 1);

        #pragma unroll
        for (int ks = 0; ks < BK / 8; ks++) {
            uint32_t a[2][4];
            #pragma unroll
            for (int mt = 0; mt < 2; mt++) {
                const float* ab = &As[(buf * BM + wm * 32 + mt * 16 + g) * KSTR + ks * 8 + c];
                a[mt][0] = f2tf32(ab[0]);
                a[mt][1] = f2tf32(ab[8 * KSTR]);
                a[mt][2] = f2tf32(ab[4]);
                a[mt][3] = f2tf32(ab[8 * KSTR + 4]);
            }
            #pragma unroll
            for (int nt = 0; nt < 4; nt++) {
                const float* b1b = &B1s[(buf * BN + wn * 32 + nt * 8 + g) * KSTR + ks * 8 + c];
                const float* b3b = &B3s[(buf * BN + wn * 32 + nt * 8 + g) * KSTR + ks * 8 + c];
                uint32_t b10 = f2tf32(b1b[0]), b11 = f2tf32(b1b[4]);
                uint32_t b30 = f2tf32(b3b[0]), b31 = f2tf32(b3b[4]);
                #pragma unroll
                for (int mt = 0; mt < 2; mt++) {
                    mma8(uacc[mt][nt], a[mt], b10, b11);
                    mma8(vacc[mt][nt], a[mt], b30, b31);
                }
            }
        }
    }

    int rem = cnt - m0;
    #pragma unroll
    for (int mt = 0; mt < 2; mt++) {
        #pragma unroll
        for (int i = 0; i < 2; i++) {
            int r = wm * 32 + mt * 16 + g + i * 8;
            if (r < rem) {
                float* hp = d_H + (size_t)(off + m0 + r) * FDIM + n0 + wn * 32;
                #pragma unroll
                for (int nt = 0; nt < 4; nt++) {
                    float u0 = uacc[mt][nt][i * 2], u1 = uacc[mt][nt][i * 2 + 1];
                    float v0 = vacc[mt][nt][i * 2], v1 = vacc[mt][nt][i * 2 + 1];
                    float h0 = u0 / (1.f + __expf(-u0)) * v0;
                    float h1 = u1 / (1.f + __expf(-u1)) * v1;
                    hp[nt * 8 + c * 2]     = h0;
                    hp[nt * 8 + c * 2 + 1] = h1;
                }
            }
        }
    }
}

// out[token, n0:n0+BN] = (H[slot] @ W2[e]^T) * prob[token]
__global__ __launch_bounds__(256, 1)
void gemm2_kernel(const float* __restrict__ w2, float* __restrict__ out) {
    int e   = blockIdx.z;
    int off = d_offsets[e];
    int cnt = d_offsets[e + 1] - off;
    int m0  = blockIdx.y * BM;
    if (m0 >= cnt) return;
    int n0 = blockIdx.x * BN;

    extern __shared__ float smem[];
    float* As = smem;                 // [2][BM][KSTR]
    float* Bs = As + 2 * BM * KSTR;   // [2][BN][KSTR]
    int tid = threadIdx.x;

    auto load_stage = [&](int kk, int buf) {
        #pragma unroll
        for (int p = 0; p < 4; p++) {
            int idx = p * 256 + tid;
            int m = idx >> 3, kq = idx & 7;
            int mi = m0 + m; if (mi >= cnt) mi = cnt - 1;
            cp16(&As[(buf * BM + m) * KSTR + kq * 4],
                 d_H + (size_t)(off + mi) * FDIM + kk + kq * 4);
        }
        #pragma unroll
        for (int p = 0; p < 2; p++) {
            int idx = p * 256 + tid;
            int n = idx >> 3, kq = idx & 7;
            cp16(&Bs[(buf * BN + n) * KSTR + kq * 4],
                 w2 + ((size_t)e * DMODEL + n0 + n) * FDIM + kk + kq * 4);
        }
        cp_commit();
    };
    load_stage(0, 0);

    float acc[2][4][4];
    #pragma unroll
    for (int a1 = 0; a1 < 2; a1++)
        #pragma unroll
        for (int a2 = 0; a2 < 4; a2++)
            #pragma unroll
            for (int a3 = 0; a3 < 4; a3++) acc[a1][a2][a3] = 0.f;

    int warp = tid >> 5, lane = tid & 31;
    int wm = warp >> 1, wn = warp & 1;
    int g = lane >> 2, c = lane & 3;

    const int NIT = FDIM / BK;        // 128
    for (int it = 0; it < NIT; it++) {
        int buf = it & 1;
        cp_wait0();
        __syncthreads();
        if (it + 1 < NIT) load_stage((it + 1) * BK, buf ^ 1);

        #pragma unroll
        for (int ks = 0; ks < BK / 8; ks++) {
            uint32_t a[2][4];
            #pragma unroll
            for (int mt = 0; mt < 2; mt++) {
                const float* ab = &As[(buf * BM + wm * 32 + mt * 16 + g) * KSTR + ks * 8 + c];
                a[mt][0] = f2tf32(ab[0]);
                a[mt][1] = f2tf32(ab[8 * KSTR]);
                a[mt][2] = f2tf32(ab[4]);
                a[mt][3] = f2tf32(ab[8 * KSTR + 4]);
            }
            #pragma unroll
            for (int nt = 0; nt < 4; nt++) {
                const float* bb = &Bs[(buf * BN + wn * 32 + nt * 8 + g) * KSTR + ks * 8 + c];
                uint32_t b0 = f2tf32(bb[0]), b1 = f2tf32(bb[4]);
                #pragma unroll
                for (int mt = 0; mt < 2; mt++) mma8(acc[mt][nt], a[mt], b0, b1);
            }
        }
    }

    int rem = cnt - m0;
    #pragma unroll
    for (int mt = 0; mt < 2; mt++) {
        #pragma unroll
        for (int i = 0; i < 2; i++) {
            int r = wm * 32 + mt * 16 + g + i * 8;
            if (r < rem) {
                int slot  = off + m0 + r;
                int token = d_perm[slot];
                float ps  = d_prob[token];
                float* op = out + (size_t)token * DMODEL + n0 + wn * 32;
                #pragma unroll
                for (int nt = 0; nt < 4; nt++) {
                    op[nt * 8 + c * 2]     = acc[mt][nt][i * 2]     * ps;
                    op[nt * 8 + c * 2 + 1] = acc[mt][nt][i * 2 + 1] * ps;
                }
            }
        }
    }
}

// ---------------- launch ----------------
extern "C" void kernel_launch(void* const* d_in, const int* in_sizes, int n_in,
                              void* d_out, int out_size) {
    const float* x  = (const float*)d_in[0];
    const float* gw = (const float*)d_in[1];
    const float* w1 = (const float*)d_in[2];
    const float* w2 = (const float*)d_in[3];
    const float* w3 = (const float*)d_in[4];
    float* out = (float*)d_out;

    int N = in_sizes[0] / DMODEL;   // 4096
    if (N > NMAX) N = NMAX;

    const int SMEM1 = (2 * BM * KSTR + 2 * BN * KSTR * 2) * 4 + BM * 4; // 74240 B
    const int SMEM2 = (2 * BM * KSTR + 2 * BN * KSTR) * 4;              // 55296 B
    cudaFuncSetAttribute(gemm1_kernel, cudaFuncAttributeMaxDynamicSharedMemorySize, SMEM1);
    cudaFuncSetAttribute(gemm2_kernel, cudaFuncAttributeMaxDynamicSharedMemorySize, SMEM2);

    float* aux_out = (out_size > N * DMODEL) ? (out + (size_t)N * DMODEL) : nullptr;

    init_kernel<<<1, 32>>>();
    gating_kernel<<<(N + 7) / 8, 256>>>(x, gw, N);
    offsets_kernel<<<1, 32>>>(N, aux_out);
    scatter_kernel<<<(N + 255) / 256, 256>>>(N);

    int mtiles = (N + BM - 1) / BM;                 // worst case: all tokens in one expert
    dim3 g1(FDIM / BN, mtiles, NEXP);               // (64, 32, 8)
    gemm1_kernel<<<g1, 256, SMEM1>>>(x, w1, w3);

    dim3 g2(DMODEL / BN, mtiles, NEXP);             // (16, 32, 8)
    gemm2_kernel<<<g2, 256, SMEM2>>>(w2, out);
}

// round 6
// speedup vs baseline: 1.9443x; 1.9443x over previous
#include <cuda_runtime.h>
#include <cuda_fp16.h>
#include <cstdint>
#include <cstddef>

#define DMODEL 1024
#define FDIM   4096
#define NEXP   8
#define NMAX   4096
#define BK     64          // 64 fp16 = 128B = one swizzle row

#define BM 128
#define BN 64

// ---------------- device scratch (static only) ----------------
__device__ __half d_Hh[(size_t)NMAX * FDIM];          // 32 MB fp16 intermediate
__device__ __half d_xh[(size_t)NMAX * DMODEL];        // 8 MB
__device__ __half d_w1h[(size_t)NEXP * FDIM * DMODEL];// 64 MB
__device__ __half d_w3h[(size_t)NEXP * FDIM * DMODEL];
__device__ __half d_w2h[(size_t)NEXP * DMODEL * FDIM];
__device__ int   d_idx[NMAX];
__device__ float d_prob[NMAX];
__device__ int   d_counts[NEXP];
__device__ float d_imp[NEXP];
__device__ int   d_offsets[NEXP + 1];
__device__ int   d_cursor[NEXP];
__device__ int   d_perm[NMAX];

// ---------------- helpers ----------------
__device__ __forceinline__ uint32_t smem_u32(const void* p) {
    return (uint32_t)__cvta_generic_to_shared(p);
}
__device__ __forceinline__ void cpa16(uint32_t s, const __half* g) {
    asm volatile("cp.async.cg.shared.global [%0], [%1], 16;" :: "r"(s), "l"(g));
}
__device__ __forceinline__ void cp_commit() { asm volatile("cp.async.commit_group;"); }
__device__ __forceinline__ void cp_wait0()  { asm volatile("cp.async.wait_group 0;" ::: "memory"); }

__device__ __forceinline__ void ldmx4(uint32_t* r, uint32_t a) {
    asm volatile("ldmatrix.sync.aligned.m8n8.x4.shared.b16 {%0,%1,%2,%3}, [%4];"
                 : "=r"(r[0]), "=r"(r[1]), "=r"(r[2]), "=r"(r[3]) : "r"(a));
}
// D += A(16x16) * B(16x8), fp16 in, f32 accum
__device__ __forceinline__ void mma16(float* c, const uint32_t* a, uint32_t b0, uint32_t b1) {
    asm volatile(
        "mma.sync.aligned.m16n8k16.row.col.f32.f16.f16.f32 "
        "{%0,%1,%2,%3},{%4,%5,%6,%7},{%8,%9},{%0,%1,%2,%3};"
        : "+f"(c[0]), "+f"(c[1]), "+f"(c[2]), "+f"(c[3])
        : "r"(a[0]), "r"(a[1]), "r"(a[2]), "r"(a[3]), "r"(b0), "r"(b1));
}

// swizzled byte offset inside a tile: row * 128B + xor'd 16B unit
__device__ __forceinline__ uint32_t swz(int row, int unit) {
    return (uint32_t)(row * 128 + ((unit ^ (row & 7)) << 4));
}

// ---------------- prep: f32 -> fp16 ----------------
__global__ void cvt_kernel(const float* __restrict__ s, __half* __restrict__ d, int n4) {
    int stride = gridDim.x * blockDim.x;
    for (int i = blockIdx.x * blockDim.x + threadIdx.x; i < n4; i += stride) {
        float4 v = ((const float4*)s)[i];
        __half2 h0 = __floats2half2_rn(v.x, v.y);
        __half2 h1 = __floats2half2_rn(v.z, v.w);
        ((__half2*)d)[2 * i]     = h0;
        ((__half2*)d)[2 * i + 1] = h1;
    }
}

// ---------------- gating / routing (unchanged from R4, f32) ----------------
__global__ void init_kernel() {
    int t = threadIdx.x;
    if (t < NEXP) { d_counts[t] = 0; d_imp[t] = 0.f; }
}

__global__ void gating_kernel(const float* __restrict__ x,
                              const float* __restrict__ gw, int N) {
    __shared__ float sgw[NEXP * DMODEL];
    __shared__ float s_imp[NEXP];
    __shared__ int   s_cnt[NEXP];
    int tid = threadIdx.x;
    for (int i = tid; i < NEXP * DMODEL; i += blockDim.x) sgw[i] = gw[i];
    if (tid < NEXP) { s_imp[tid] = 0.f; s_cnt[tid] = 0; }
    __syncthreads();

    int warp = tid >> 5, lane = tid & 31;
    int n = blockIdx.x * 8 + warp;
    if (n < N) {
        float acc[NEXP];
        #pragma unroll
        for (int e = 0; e < NEXP; e++) acc[e] = 0.f;
        const float* xr = x + (size_t)n * DMODEL;
        for (int i = lane; i < DMODEL; i += 32) {
            float xv = xr[i];
            #pragma unroll
            for (int e = 0; e < NEXP; e++) acc[e] += xv * sgw[e * DMODEL + i];
        }
        #pragma unroll
        for (int e = 0; e < NEXP; e++) {
            #pragma unroll
            for (int o = 16; o > 0; o >>= 1)
                acc[e] += __shfl_down_sync(0xffffffffu, acc[e], o);
        }
        if (lane == 0) {
            float m = acc[0]; int am = 0;
            #pragma unroll
            for (int e = 1; e < NEXP; e++) if (acc[e] > m) { m = acc[e]; am = e; }
            float p[NEXP]; float s = 0.f;
            #pragma unroll
            for (int e = 0; e < NEXP; e++) { p[e] = expf(acc[e] - m); s += p[e]; }
            float inv = 1.f / s;
            #pragma unroll
            for (int e = 0; e < NEXP; e++) atomicAdd(&s_imp[e], p[e] * inv);
            d_idx[n]  = am;
            d_prob[n] = p[am] * inv;
            atomicAdd(&s_cnt[am], 1);
        }
    }
    __syncthreads();
    if (tid < NEXP) {
        atomicAdd(&d_imp[tid],    s_imp[tid]);
        atomicAdd(&d_counts[tid], s_cnt[tid]);
    }
}

__global__ void offsets_kernel(int N, float* aux_out) {
    if (threadIdx.x == 0) {
        int off = 0;
        #pragma unroll
        for (int e = 0; e < NEXP; e++) {
            d_offsets[e] = off; off += d_counts[e]; d_cursor[e] = 0;
        }
        d_offsets[NEXP] = off;
        if (aux_out) {
            float invN = 1.f / (float)N;
            float aux = 0.f;
            #pragma unroll
            for (int e = 0; e < NEXP; e++)
                aux += ((float)d_counts[e] * invN) * (d_imp[e] * invN);
            *aux_out = aux * (float)NEXP * 0.01f;
        }
    }
}

__global__ void scatter_kernel(int N) {
    int n = blockIdx.x * blockDim.x + threadIdx.x;
    if (n < N) {
        int e = d_idx[n];
        int pos = d_offsets[e] + atomicAdd(&d_cursor[e], 1);
        d_perm[pos] = n;
    }
}

// ================ GEMM1: H = silu(X W1^T) * (X W3^T), fp16 mma ================
// smem bytes: rows[128] @0, A @1024 (2x16KB), B1 @33792 (2x8KB), B3 @50176 (2x8KB)
#define G1_SMEM 66560

__global__ __launch_bounds__(256, 1)
void gemm1_kernel() {
    int e   = blockIdx.z;
    int off = d_offsets[e];
    int cnt = d_offsets[e + 1] - off;
    int m0  = blockIdx.y * BM;
    if (m0 >= cnt) return;
    int n0 = blockIdx.x * BN;

    extern __shared__ char smem[];
    int* rows = (int*)smem;
    uint32_t sb  = smem_u32(smem);
    uint32_t sbA = sb + 1024, sbB1 = sb + 33792, sbB3 = sb + 50176;

    int tid = threadIdx.x, wid = tid >> 5, lane = tid & 31;
    int wm = wid >> 1, wn = wid & 1;          // 4(m) x 2(n) warps; warp tile 32x32

    for (int i = tid; i < BM; i += 256) {
        int mi = m0 + i;
        rows[i] = d_perm[off + (mi < cnt ? mi : 0)];
    }
    __syncthreads();

    auto fill = [&](int it, int buf) {
        int kk = it * BK;
        uint32_t Ab = sbA + buf * 16384, B1b = sbB1 + buf * 8192, B3b = sbB3 + buf * 8192;
        #pragma unroll
        for (int p = 0; p < 4; p++) {             // A: 128 rows x 8 units
            int idx = p * 256 + tid;
            int r = idx >> 3, u = idx & 7;
            cpa16(Ab + swz(r, u), d_xh + (size_t)rows[r] * DMODEL + kk + u * 8);
        }
        #pragma unroll
        for (int p = 0; p < 2; p++) {             // B1/B3: 64 rows x 8 units
            int idx = p * 256 + tid;
            int r = idx >> 3, u = idx & 7;
            size_t gb = ((size_t)e * FDIM + n0 + r) * DMODEL + kk + u * 8;
            uint32_t so = swz(r, u);
            cpa16(B1b + so, d_w1h + gb);
            cpa16(B3b + so, d_w3h + gb);
        }
        cp_commit();
    };
    fill(0, 0);

    // ldmatrix lane-partition constants
    int pa_r = ((lane >> 3) & 1) * 8 + (lane & 7);  // A: grp0/2 rows+0, grp1/3 rows+8
    int pa_u = lane >> 4;                           // A: grps 0,1 k-lo; 2,3 k-hi
    int pb_r = ((lane >> 4) << 3) + (lane & 7);     // B: grps 0,1 rows+0; 2,3 rows+8
    int pb_u = (lane >> 3) & 1;                     // B: grp0/2 k-lo, grp1/3 k-hi
    int rowA[2], rowB[2];
    #pragma unroll
    for (int mt = 0; mt < 2; mt++) rowA[mt] = wm * 32 + mt * 16 + pa_r;
    #pragma unroll
    for (int np = 0; np < 2; np++) rowB[np] = wn * 32 + np * 16 + pb_r;

    float uacc[2][4][4], vacc[2][4][4];
    #pragma unroll
    for (int a = 0; a < 2; a++)
        #pragma unroll
        for (int b = 0; b < 4; b++)
            #pragma unroll
            for (int q = 0; q < 4; q++) { uacc[a][b][q] = 0.f; vacc[a][b][q] = 0.f; }

    const int NIT = DMODEL / BK;   // 16
    for (int it = 0; it < NIT; it++) {
        int buf = it & 1;
        cp_wait0();
        __syncthreads();
        if (it + 1 < NIT) fill(it + 1, buf ^ 1);

        uint32_t Ab = sbA + buf * 16384, B1b = sbB1 + buf * 8192, B3b = sbB3 + buf * 8192;
        #pragma unroll
        for (int ks = 0; ks < 4; ks++) {
            uint32_t a[2][4];
            #pragma unroll
            for (int mt = 0; mt < 2; mt++)
                ldmx4(a[mt], Ab + swz(rowA[mt], ks * 2 + pa_u));
            #pragma unroll
            for (int np = 0; np < 2; np++) {
                uint32_t b1[4], b3[4];
                uint32_t so = swz(rowB[np], ks * 2 + pb_u);
                ldmx4(b1, B1b + so);
                ldmx4(b3, B3b + so);
                #pragma unroll
                for (int h = 0; h < 2; h++)
                    #pragma unroll
                    for (int mt = 0; mt < 2; mt++) {
                        mma16(uacc[mt][np * 2 + h], a[mt], b1[h * 2], b1[h * 2 + 1]);
                        mma16(vacc[mt][np * 2 + h], a[mt], b3[h * 2], b3[h * 2 + 1]);
                    }
            }
        }
    }

    // epilogue: silu(u)*v -> fp16 H
    int g = lane >> 2, c2 = (lane & 3) * 2;
    #pragma unroll
    for (int mt = 0; mt < 2; mt++) {
        #pragma unroll
        for (int i = 0; i < 2; i++) {
            int r = m0 + wm * 32 + mt * 16 + g + i * 8;
            if (r < cnt) {
                __half* hp = d_Hh + (size_t)(off + r) * FDIM + n0 + wn * 32;
                #pragma unroll
                for (int nt = 0; nt < 4; nt++) {
                    float u0 = uacc[mt][nt][i * 2], u1 = uacc[mt][nt][i * 2 + 1];
                    float v0 = vacc[mt][nt][i * 2], v1 = vacc[mt][nt][i * 2 + 1];
                    float h0 = u0 / (1.f + __expf(-u0)) * v0;
                    float h1 = u1 / (1.f + __expf(-u1)) * v1;
                    *(__half2*)(hp + nt * 8 + c2) = __floats2half2_rn(h0, h1);
                }
            }
        }
    }
}

// ================ GEMM2: out = (H @ W2^T) * prob, fp16 mma ================
// smem bytes: A @0 (2x16KB), B @32768 (2x8KB)
#define G2_SMEM 49152

__global__ __launch_bounds__(256, 2)
void gemm2_kernel(float* __restrict__ out) {
    int e   = blockIdx.z;
    int off = d_offsets[e];
    int cnt = d_offsets[e + 1] - off;
    int m0  = blockIdx.y * BM;
    if (m0 >= cnt) return;
    int n0 = blockIdx.x * BN;

    extern __shared__ char smem[];
    uint32_t sb  = smem_u32(smem);
    uint32_t sbA = sb, sbB = sb + 32768;

    int tid = threadIdx.x, wid = tid >> 5, lane = tid & 31;
    int wm = wid >> 1, wn = wid & 1;

    auto fill = [&](int it, int buf) {
        int kk = it * BK;
        uint32_t Ab = sbA + buf * 16384, Bb = sbB + buf * 8192;
        #pragma unroll
        for (int p = 0; p < 4; p++) {             // A(H): 128 rows
            int idx = p * 256 + tid;
            int r = idx >> 3, u = idx & 7;
            int mi = m0 + r; if (mi >= cnt) mi = cnt - 1;
            cpa16(Ab + swz(r, u), d_Hh + (size_t)(off + mi) * FDIM + kk + u * 8);
        }
        #pragma unroll
        for (int p = 0; p < 2; p++) {             // B(w2): 64 rows
            int idx = p * 256 + tid;
            int r = idx >> 3, u = idx & 7;
            cpa16(Bb + swz(r, u),
                  d_w2h + ((size_t)e * DMODEL + n0 + r) * FDIM + kk + u * 8);
        }
        cp_commit();
    };
    fill(0, 0);

    int pa_r = ((lane >> 3) & 1) * 8 + (lane & 7);
    int pa_u = lane >> 4;
    int pb_r = ((lane >> 4) << 3) + (lane & 7);
    int pb_u = (lane >> 3) & 1;
    int rowA[2], rowB[2];
    #pragma unroll
    for (int mt = 0; mt < 2; mt++) rowA[mt] = wm * 32 + mt * 16 + pa_r;
    #pragma unroll
    for (int np = 0; np < 2; np++) rowB[np] = wn * 32 + np * 16 + pb_r;

    float acc[2][4][4];
    #pragma unroll
    for (int a = 0; a < 2; a++)
        #pragma unroll
        for (int b = 0; b < 4; b++)
            #pragma unroll
            for (int q = 0; q < 4; q++) acc[a][b][q] = 0.f;

    const int NIT = FDIM / BK;   // 64
    for (int it = 0; it < NIT; it++) {
        int buf = it & 1;
        cp_wait0();
        __syncthreads();
        if (it + 1 < NIT) fill(it + 1, buf ^ 1);

        uint32_t Ab = sbA + buf * 16384, Bb = sbB + buf * 8192;
        #pragma unroll
        for (int ks = 0; ks < 4; ks++) {
            uint32_t a[2][4];
            #pragma unroll
            for (int mt = 0; mt < 2; mt++)
                ldmx4(a[mt], Ab + swz(rowA[mt], ks * 2 + pa_u));
            #pragma unroll
            for (int np = 0; np < 2; np++) {
                uint32_t b[4];
                ldmx4(b, Bb + swz(rowB[np], ks * 2 + pb_u));
                #pragma unroll
                for (int h = 0; h < 2; h++)
                    #pragma unroll
                    for (int mt = 0; mt < 2; mt++)
                        mma16(acc[mt][np * 2 + h], a[mt], b[h * 2], b[h * 2 + 1]);
            }
        }
    }

    int g = lane >> 2, c2 = (lane & 3) * 2;
    #pragma unroll
    for (int mt = 0; mt < 2; mt++) {
        #pragma unroll
        for (int i = 0; i < 2; i++) {
            int r = m0 + wm * 32 + mt * 16 + g + i * 8;
            if (r < cnt) {
                int token = d_perm[off + r];
                float ps  = d_prob[token];
                float* op = out + (size_t)token * DMODEL + n0 + wn * 32;
                #pragma unroll
                for (int nt = 0; nt < 4; nt++) {
                    float2 o;
                    o.x = acc[mt][nt][i * 2]     * ps;
                    o.y = acc[mt][nt][i * 2 + 1] * ps;
                    *(float2*)(op + nt * 8 + c2) = o;
                }
            }
        }
    }
}

// ---------------- launch ----------------
extern "C" void kernel_launch(void* const* d_in, const int* in_sizes, int n_in,
                              void* d_out, int out_size) {
    const float* x  = (const float*)d_in[0];
    const float* gw = (const float*)d_in[1];
    const float* w1 = (const float*)d_in[2];
    const float* w2 = (const float*)d_in[3];
    const float* w3 = (const float*)d_in[4];
    float* out = (float*)d_out;

    int N = in_sizes[0] / DMODEL;   // 4096
    if (N > NMAX) N = NMAX;

    cudaFuncSetAttribute(gemm1_kernel, cudaFuncAttributeMaxDynamicSharedMemorySize, G1_SMEM);
    cudaFuncSetAttribute(gemm2_kernel, cudaFuncAttributeMaxDynamicSharedMemorySize, G2_SMEM);

    float* aux_out = (out_size > N * DMODEL) ? (out + (size_t)N * DMODEL) : nullptr;

    // resolve static device buffers
    __half *xh, *w1h, *w2h, *w3h;
    cudaGetSymbolAddress((void**)&xh,  d_xh);
    cudaGetSymbolAddress((void**)&w1h, d_w1h);
    cudaGetSymbolAddress((void**)&w2h, d_w2h);
    cudaGetSymbolAddress((void**)&w3h, d_w3h);

    // f32 -> fp16 prep
    cvt_kernel<<<592, 256>>>(x,  xh,  N * DMODEL / 4);
    cvt_kernel<<<592, 256>>>(w1, w1h, NEXP * FDIM * DMODEL / 4);
    cvt_kernel<<<592, 256>>>(w3, w3h, NEXP * FDIM * DMODEL / 4);
    cvt_kernel<<<592, 256>>>(w2, w2h, NEXP * DMODEL * FDIM / 4);

    init_kernel<<<1, 32>>>();
    gating_kernel<<<(N + 7) / 8, 256>>>(x, gw, N);
    offsets_kernel<<<1, 32>>>(N, aux_out);
    scatter_kernel<<<(N + 255) / 256, 256>>>(N);

    int mtiles = (N + BM - 1) / BM;            // 32 worst-case
    dim3 g1(FDIM / BN, mtiles, NEXP);          // (64, 32, 8)
    gemm1_kernel<<<g1, 256, G1_SMEM>>>();

    dim3 g2(DMODEL / BN, mtiles, NEXP);        // (16, 32, 8)
    gemm2_kernel<<<g2, 256, G2_SMEM>>>(out);
}